// round 2
// baseline (speedup 1.0000x reference)
#include <cuda_runtime.h>
#include <math.h>

// Problem dims (fixed)
#define BATCH  8192
#define IN_DIM 4096
#define MEMD   256
#define KDIM   4352      // MEMD + IN_DIM
#define NTOT   1024      // 512 (W1) + 256 (Wd) + 256 (Wu)

// Scratch for pre-activations of the fused big GEMM:
// cols [0,512)   : combined@W1 + b1
// cols [512,768) : combined@Wd + bd
// cols [768,1024): combined@Wu + bu
__device__ float g_Y[(size_t)BATCH * NTOT];

// ---------------------------------------------------------------------------
// Kernel 1: fused GEMM  Y = [h|x] @ [W1|Wd|Wu] + [b1|bd|bu]
// 128x128x8 tiles, 256 threads, 8x8 register microtile, double-buffered smem.
// ---------------------------------------------------------------------------
__global__ __launch_bounds__(256)
void gemm1_kernel(const float* __restrict__ x, const float* __restrict__ h,
                  const float* __restrict__ W1, const float* __restrict__ Wd,
                  const float* __restrict__ Wu,
                  const float* __restrict__ b1, const float* __restrict__ bd,
                  const float* __restrict__ bu)
{
    constexpr int BM = 128, BN = 128, BK = 8;
    __shared__ float As[2][BK * BM];   // transposed: As[k][m]
    __shared__ float Bs[2][BK * BN];   // Bs[k][n]

    const int tid = threadIdx.x;
    const int bx = blockIdx.x;   // n-tile 0..7
    const int by = blockIdx.y;   // m-tile 0..63

    // Select source weight matrix / bias for this n-tile (tiles are aligned
    // to matrix boundaries: 0-3 -> W1, 4-5 -> Wd, 6-7 -> Wu).
    const float* Wsrc; const float* bsrc; int ldw, ncol0;
    if (bx < 4)      { Wsrc = W1; bsrc = b1; ldw = 512; ncol0 = bx * 128; }
    else if (bx < 6) { Wsrc = Wd; bsrc = bd; ldw = 256; ncol0 = (bx - 4) * 128; }
    else             { Wsrc = Wu; bsrc = bu; ldw = 256; ncol0 = (bx - 6) * 128; }

    // A-tile load indices: 128 rows x 8 k, one float4 per thread along k
    const int a_row = tid >> 1;            // 0..127
    const int a_k   = (tid & 1) << 2;      // 0 or 4
    const int m_glob = by * BM + a_row;
    // B-tile load indices: 8 k x 128 n, one float4 per thread along n
    const int b_k = tid >> 5;              // 0..7
    const int b_n = (tid & 31) << 2;       // 0..124

    const int ty = tid >> 4;               // 0..15
    const int tx = tid & 15;               // 0..15

    float acc[8][8];
    #pragma unroll
    for (int i = 0; i < 8; i++)
        #pragma unroll
        for (int j = 0; j < 8; j++) acc[i][j] = 0.f;

    const int NTILES = KDIM / BK;          // 544

    // ---- prologue: load tile 0 into buffer 0
    {
        int kg = a_k;  // tile 0
        float4 va;
        if (kg < MEMD) va = *reinterpret_cast<const float4*>(h + (size_t)m_glob * MEMD + kg);
        else           va = *reinterpret_cast<const float4*>(x + (size_t)m_glob * IN_DIM + (kg - MEMD));
        As[0][(a_k + 0) * BM + a_row] = va.x;
        As[0][(a_k + 1) * BM + a_row] = va.y;
        As[0][(a_k + 2) * BM + a_row] = va.z;
        As[0][(a_k + 3) * BM + a_row] = va.w;
        float4 vb = *reinterpret_cast<const float4*>(Wsrc + (size_t)b_k * ldw + ncol0 + b_n);
        *reinterpret_cast<float4*>(&Bs[0][b_k * BN + b_n]) = vb;
    }
    __syncthreads();

    for (int kt = 0; kt < NTILES; ++kt) {
        const int buf = kt & 1;
        const bool more = (kt + 1 < NTILES);
        float4 an, bn;
        if (more) {
            int kg = (kt + 1) * BK + a_k;
            if (kg < MEMD) an = *reinterpret_cast<const float4*>(h + (size_t)m_glob * MEMD + kg);
            else           an = *reinterpret_cast<const float4*>(x + (size_t)m_glob * IN_DIM + (kg - MEMD));
            bn = *reinterpret_cast<const float4*>(Wsrc + (size_t)((kt + 1) * BK + b_k) * ldw + ncol0 + b_n);
        }

        #pragma unroll
        for (int kk = 0; kk < BK; ++kk) {
            float4 a0 = *reinterpret_cast<const float4*>(&As[buf][kk * BM + ty * 4]);
            float4 a1 = *reinterpret_cast<const float4*>(&As[buf][kk * BM + 64 + ty * 4]);
            float4 c0 = *reinterpret_cast<const float4*>(&Bs[buf][kk * BN + tx * 4]);
            float4 c1 = *reinterpret_cast<const float4*>(&Bs[buf][kk * BN + 64 + tx * 4]);
            float av[8] = {a0.x, a0.y, a0.z, a0.w, a1.x, a1.y, a1.z, a1.w};
            float bv[8] = {c0.x, c0.y, c0.z, c0.w, c1.x, c1.y, c1.z, c1.w};
            #pragma unroll
            for (int i = 0; i < 8; i++)
                #pragma unroll
                for (int j = 0; j < 8; j++)
                    acc[i][j] = fmaf(av[i], bv[j], acc[i][j]);
        }

        if (more) {
            const int nb = buf ^ 1;
            As[nb][(a_k + 0) * BM + a_row] = an.x;
            As[nb][(a_k + 1) * BM + a_row] = an.y;
            As[nb][(a_k + 2) * BM + a_row] = an.z;
            As[nb][(a_k + 3) * BM + a_row] = an.w;
            *reinterpret_cast<float4*>(&Bs[nb][b_k * BN + b_n]) = bn;
        }
        __syncthreads();
    }

    // ---- epilogue: add bias, write Y
    #pragma unroll
    for (int i = 0; i < 8; i++) {
        const int mloc = (i < 4) ? (ty * 4 + i) : (64 + ty * 4 + (i - 4));
        float* yout = g_Y + (size_t)(by * BM + mloc) * NTOT + bx * BN;
        #pragma unroll
        for (int jh = 0; jh < 2; ++jh) {
            const int nl = jh * 64 + tx * 4;
            float4 v;
            v.x = acc[i][jh * 4 + 0] + bsrc[ncol0 + nl + 0];
            v.y = acc[i][jh * 4 + 1] + bsrc[ncol0 + nl + 1];
            v.z = acc[i][jh * 4 + 2] + bsrc[ncol0 + nl + 2];
            v.w = acc[i][jh * 4 + 3] + bsrc[ncol0 + nl + 3];
            *reinterpret_cast<float4*>(yout + nl) = v;
        }
    }
}

// ---------------------------------------------------------------------------
// Kernel 2: per 16 rows — LN + exact GELU, GEMM2 (512x256, W2 L2-resident),
// tanh candidate, sigmoid gates, liquid update, L2-norm rescale.
// ---------------------------------------------------------------------------
__global__ __launch_bounds__(256)
void fuse2_kernel(const float* __restrict__ h,
                  const float* __restrict__ gam, const float* __restrict__ bet,
                  const float* __restrict__ W2, const float* __restrict__ b2,
                  float* __restrict__ out)
{
    constexpr int ROWS = 16;
    __shared__ float s_t[ROWS * 512];      // GELU(LN(t)) activations
    __shared__ float s_red[2 * ROWS * 8];  // per-warp partial h^2 / nh^2 sums
    __shared__ float s_scale[ROWS];

    const int tid  = threadIdx.x;
    const int w    = tid >> 5;
    const int lane = tid & 31;
    const int row0 = blockIdx.x * ROWS;

    // ---- Phase A: LayerNorm + exact GELU, one warp per row (2 rows/warp)
    #pragma unroll
    for (int rr = 0; rr < 2; ++rr) {
        const int r = w + rr * 8;
        const float* yrow = g_Y + (size_t)(row0 + r) * NTOT;
        float vals[16];
        float s = 0.f, s2 = 0.f;
        #pragma unroll
        for (int q = 0; q < 4; q++) {
            float4 v = *reinterpret_cast<const float4*>(yrow + (lane + q * 32) * 4);
            vals[q * 4 + 0] = v.x; vals[q * 4 + 1] = v.y;
            vals[q * 4 + 2] = v.z; vals[q * 4 + 3] = v.w;
            s  += v.x + v.y + v.z + v.w;
            s2 += v.x * v.x + v.y * v.y + v.z * v.z + v.w * v.w;
        }
        #pragma unroll
        for (int o = 16; o; o >>= 1) {
            s  += __shfl_xor_sync(0xffffffffu, s,  o);
            s2 += __shfl_xor_sync(0xffffffffu, s2, o);
        }
        const float mu   = s * (1.f / 512.f);
        const float var  = s2 * (1.f / 512.f) - mu * mu;
        const float rstd = rsqrtf(var + 1e-5f);
        #pragma unroll
        for (int q = 0; q < 4; q++) {
            const int c = (lane + q * 32) * 4;
            float4 gv = *reinterpret_cast<const float4*>(gam + c);
            float4 bv = *reinterpret_cast<const float4*>(bet + c);
            float g4[4] = {gv.x, gv.y, gv.z, gv.w};
            float be4[4] = {bv.x, bv.y, bv.z, bv.w};
            #pragma unroll
            for (int e = 0; e < 4; e++) {
                float t  = (vals[q * 4 + e] - mu) * rstd * g4[e] + be4[e];
                float gl = 0.5f * t * (1.f + erff(t * 0.7071067811865475f));
                s_t[r * 512 + c + e] = gl;
            }
        }
    }
    __syncthreads();

    // ---- Phase B: GEMM2 — thread j owns output column j for all 16 rows
    const int j = tid;
    float acc[ROWS];
    #pragma unroll
    for (int r = 0; r < ROWS; r++) acc[r] = 0.f;

    #pragma unroll 4
    for (int k = 0; k < 512; k++) {
        const float wv = W2[(size_t)k * 256 + j];
        #pragma unroll
        for (int r = 0; r < ROWS; r++)
            acc[r] = fmaf(s_t[r * 512 + k], wv, acc[r]);
    }

    // ---- Phase C: gates, liquid update, norm reductions
    const float b2j = b2[j];
    #pragma unroll
    for (int r = 0; r < ROWS; r++) {
        const int rg = row0 + r;
        const float* yrow = g_Y + (size_t)rg * NTOT;
        const float hc = tanhf(acc[r] + b2j);
        const float dp = yrow[512 + j];                  // bias already added
        const float up = yrow[768 + j];
        const float dec = 1.f / (1.f + expf(-dp));
        const float ts  = 0.1f + 9.9f * dec + 1e-6f;
        const float u   = 1.f / (1.f + expf(-up));
        const float hv  = h[(size_t)rg * MEMD + j];
        const float nh  = (1.f - u) * (hv / ts) + u * hc;
        acc[r] = nh;

        float ph = hv * hv, pn = nh * nh;
        #pragma unroll
        for (int o = 16; o; o >>= 1) {
            ph += __shfl_xor_sync(0xffffffffu, ph, o);
            pn += __shfl_xor_sync(0xffffffffu, pn, o);
        }
        if (lane == 0) {
            s_red[r * 8 + w]       = ph;
            s_red[128 + r * 8 + w] = pn;
        }
    }
    __syncthreads();

    if (tid < ROWS) {
        float h2 = 0.f, n2 = 0.f;
        #pragma unroll
        for (int q = 0; q < 8; q++) {
            h2 += s_red[tid * 8 + q];
            n2 += s_red[128 + tid * 8 + q];
        }
        const float hn = fmaxf(sqrtf(h2), 1e-6f);
        const float nn = fmaxf(sqrtf(n2), 1e-12f);
        s_scale[tid] = hn / nn;
    }
    __syncthreads();

    #pragma unroll
    for (int r = 0; r < ROWS; r++)
        out[(size_t)(row0 + r) * MEMD + j] = acc[r] * s_scale[r];
}

// ---------------------------------------------------------------------------
extern "C" void kernel_launch(void* const* d_in, const int* in_sizes, int n_in,
                              void* d_out, int out_size)
{
    (void)in_sizes; (void)n_in; (void)out_size;
    const float* x   = (const float*)d_in[0];
    const float* h   = (const float*)d_in[1];
    const float* W1  = (const float*)d_in[2];
    const float* b1  = (const float*)d_in[3];
    const float* gam = (const float*)d_in[4];
    const float* bet = (const float*)d_in[5];
    const float* W2  = (const float*)d_in[6];
    const float* b2  = (const float*)d_in[7];
    const float* Wd  = (const float*)d_in[8];
    const float* bd  = (const float*)d_in[9];
    const float* Wu  = (const float*)d_in[10];
    const float* bu  = (const float*)d_in[11];
    float* out = (float*)d_out;

    dim3 grid1(NTOT / 128, BATCH / 128);   // 8 x 64
    gemm1_kernel<<<grid1, 256>>>(x, h, W1, Wd, Wu, b1, bd, bu);
    fuse2_kernel<<<BATCH / 16, 256>>>(h, gam, bet, W2, b2, out);
}

// round 3
// speedup vs baseline: 1.0015x; 1.0015x over previous
#include <cuda_runtime.h>
#include <math.h>

// Problem dims (fixed)
#define BATCH  8192
#define IN_DIM 4096
#define MEMD   256
#define KDIM   4352      // MEMD + IN_DIM
#define NTOT   1024      // 512 (W1) + 256 (Wd) + 256 (Wu)

// Scratch for pre-activations of the fused big GEMM:
// cols [0,512)   : combined@W1 + b1
// cols [512,768) : combined@Wd + bd
// cols [768,1024): combined@Wu + bu
__device__ float g_Y[(size_t)BATCH * NTOT];

// ---------------------------------------------------------------------------
// Kernel 1: fused GEMM  Y = [h|x] @ [W1|Wd|Wu] + [b1|bd|bu]
// 128x128x8 tiles, 256 threads, 8x8 register microtile, double-buffered smem.
// ---------------------------------------------------------------------------
__global__ __launch_bounds__(256)
void gemm1_kernel(const float* __restrict__ x, const float* __restrict__ h,
                  const float* __restrict__ W1, const float* __restrict__ Wd,
                  const float* __restrict__ Wu,
                  const float* __restrict__ b1, const float* __restrict__ bd,
                  const float* __restrict__ bu)
{
    constexpr int BM = 128, BN = 128, BK = 8;
    __shared__ float As[2][BK * BM];   // transposed: As[k][m]
    __shared__ float Bs[2][BK * BN];   // Bs[k][n]

    const int tid = threadIdx.x;
    const int bx = blockIdx.x;   // n-tile 0..7
    const int by = blockIdx.y;   // m-tile 0..63

    // Select source weight matrix / bias for this n-tile (tiles are aligned
    // to matrix boundaries: 0-3 -> W1, 4-5 -> Wd, 6-7 -> Wu).
    const float* Wsrc; const float* bsrc; int ldw, ncol0;
    if (bx < 4)      { Wsrc = W1; bsrc = b1; ldw = 512; ncol0 = bx * 128; }
    else if (bx < 6) { Wsrc = Wd; bsrc = bd; ldw = 256; ncol0 = (bx - 4) * 128; }
    else             { Wsrc = Wu; bsrc = bu; ldw = 256; ncol0 = (bx - 6) * 128; }

    // A-tile load indices: 128 rows x 8 k, one float4 per thread along k
    const int a_row = tid >> 1;            // 0..127
    const int a_k   = (tid & 1) << 2;      // 0 or 4
    const int m_glob = by * BM + a_row;
    // B-tile load indices: 8 k x 128 n, one float4 per thread along n
    const int b_k = tid >> 5;              // 0..7
    const int b_n = (tid & 31) << 2;       // 0..124

    const int ty = tid >> 4;               // 0..15
    const int tx = tid & 15;               // 0..15

    float acc[8][8];
    #pragma unroll
    for (int i = 0; i < 8; i++)
        #pragma unroll
        for (int j = 0; j < 8; j++) acc[i][j] = 0.f;

    const int NTILES = KDIM / BK;          // 544

    // ---- prologue: load tile 0 into buffer 0
    {
        int kg = a_k;  // tile 0
        float4 va;
        if (kg < MEMD) va = *reinterpret_cast<const float4*>(h + (size_t)m_glob * MEMD + kg);
        else           va = *reinterpret_cast<const float4*>(x + (size_t)m_glob * IN_DIM + (kg - MEMD));
        As[0][(a_k + 0) * BM + a_row] = va.x;
        As[0][(a_k + 1) * BM + a_row] = va.y;
        As[0][(a_k + 2) * BM + a_row] = va.z;
        As[0][(a_k + 3) * BM + a_row] = va.w;
        float4 vb = *reinterpret_cast<const float4*>(Wsrc + (size_t)b_k * ldw + ncol0 + b_n);
        *reinterpret_cast<float4*>(&Bs[0][b_k * BN + b_n]) = vb;
    }
    __syncthreads();

    for (int kt = 0; kt < NTILES; ++kt) {
        const int buf = kt & 1;
        const bool more = (kt + 1 < NTILES);
        float4 an, bn;
        if (more) {
            int kg = (kt + 1) * BK + a_k;
            if (kg < MEMD) an = *reinterpret_cast<const float4*>(h + (size_t)m_glob * MEMD + kg);
            else           an = *reinterpret_cast<const float4*>(x + (size_t)m_glob * IN_DIM + (kg - MEMD));
            bn = *reinterpret_cast<const float4*>(Wsrc + (size_t)((kt + 1) * BK + b_k) * ldw + ncol0 + b_n);
        }

        #pragma unroll
        for (int kk = 0; kk < BK; ++kk) {
            float4 a0 = *reinterpret_cast<const float4*>(&As[buf][kk * BM + ty * 4]);
            float4 a1 = *reinterpret_cast<const float4*>(&As[buf][kk * BM + 64 + ty * 4]);
            float4 c0 = *reinterpret_cast<const float4*>(&Bs[buf][kk * BN + tx * 4]);
            float4 c1 = *reinterpret_cast<const float4*>(&Bs[buf][kk * BN + 64 + tx * 4]);
            float av[8] = {a0.x, a0.y, a0.z, a0.w, a1.x, a1.y, a1.z, a1.w};
            float bv[8] = {c0.x, c0.y, c0.z, c0.w, c1.x, c1.y, c1.z, c1.w};
            #pragma unroll
            for (int i = 0; i < 8; i++)
                #pragma unroll
                for (int j = 0; j < 8; j++)
                    acc[i][j] = fmaf(av[i], bv[j], acc[i][j]);
        }

        if (more) {
            const int nb = buf ^ 1;
            As[nb][(a_k + 0) * BM + a_row] = an.x;
            As[nb][(a_k + 1) * BM + a_row] = an.y;
            As[nb][(a_k + 2) * BM + a_row] = an.z;
            As[nb][(a_k + 3) * BM + a_row] = an.w;
            *reinterpret_cast<float4*>(&Bs[nb][b_k * BN + b_n]) = bn;
        }
        __syncthreads();
    }

    // ---- epilogue: add bias, write Y
    #pragma unroll
    for (int i = 0; i < 8; i++) {
        const int mloc = (i < 4) ? (ty * 4 + i) : (64 + ty * 4 + (i - 4));
        float* yout = g_Y + (size_t)(by * BM + mloc) * NTOT + bx * BN;
        #pragma unroll
        for (int jh = 0; jh < 2; ++jh) {
            const int nl = jh * 64 + tx * 4;
            float4 v;
            v.x = acc[i][jh * 4 + 0] + bsrc[ncol0 + nl + 0];
            v.y = acc[i][jh * 4 + 1] + bsrc[ncol0 + nl + 1];
            v.z = acc[i][jh * 4 + 2] + bsrc[ncol0 + nl + 2];
            v.w = acc[i][jh * 4 + 3] + bsrc[ncol0 + nl + 3];
            *reinterpret_cast<float4*>(yout + nl) = v;
        }
    }
}

// ---------------------------------------------------------------------------
// Kernel 2: per 16 rows — LN + exact GELU, GEMM2 (512x256, W2 L2-resident),
// tanh candidate, sigmoid gates, liquid update, L2-norm rescale.
// ---------------------------------------------------------------------------
__global__ __launch_bounds__(256)
void fuse2_kernel(const float* __restrict__ h,
                  const float* __restrict__ gam, const float* __restrict__ bet,
                  const float* __restrict__ W2, const float* __restrict__ b2,
                  float* __restrict__ out)
{
    constexpr int ROWS = 16;
    __shared__ float s_t[ROWS * 512];      // GELU(LN(t)) activations
    __shared__ float s_red[2 * ROWS * 8];  // per-warp partial h^2 / nh^2 sums
    __shared__ float s_scale[ROWS];

    const int tid  = threadIdx.x;
    const int w    = tid >> 5;
    const int lane = tid & 31;
    const int row0 = blockIdx.x * ROWS;

    // ---- Phase A: LayerNorm + exact GELU, one warp per row (2 rows/warp)
    #pragma unroll
    for (int rr = 0; rr < 2; ++rr) {
        const int r = w + rr * 8;
        const float* yrow = g_Y + (size_t)(row0 + r) * NTOT;
        float vals[16];
        float s = 0.f, s2 = 0.f;
        #pragma unroll
        for (int q = 0; q < 4; q++) {
            float4 v = *reinterpret_cast<const float4*>(yrow + (lane + q * 32) * 4);
            vals[q * 4 + 0] = v.x; vals[q * 4 + 1] = v.y;
            vals[q * 4 + 2] = v.z; vals[q * 4 + 3] = v.w;
            s  += v.x + v.y + v.z + v.w;
            s2 += v.x * v.x + v.y * v.y + v.z * v.z + v.w * v.w;
        }
        #pragma unroll
        for (int o = 16; o; o >>= 1) {
            s  += __shfl_xor_sync(0xffffffffu, s,  o);
            s2 += __shfl_xor_sync(0xffffffffu, s2, o);
        }
        const float mu   = s * (1.f / 512.f);
        const float var  = s2 * (1.f / 512.f) - mu * mu;
        const float rstd = rsqrtf(var + 1e-5f);
        #pragma unroll
        for (int q = 0; q < 4; q++) {
            const int c = (lane + q * 32) * 4;
            float4 gv = *reinterpret_cast<const float4*>(gam + c);
            float4 bv = *reinterpret_cast<const float4*>(bet + c);
            float g4[4] = {gv.x, gv.y, gv.z, gv.w};
            float be4[4] = {bv.x, bv.y, bv.z, bv.w};
            #pragma unroll
            for (int e = 0; e < 4; e++) {
                float t  = (vals[q * 4 + e] - mu) * rstd * g4[e] + be4[e];
                float gl = 0.5f * t * (1.f + erff(t * 0.7071067811865475f));
                s_t[r * 512 + c + e] = gl;
            }
        }
    }
    __syncthreads();

    // ---- Phase B: GEMM2 — thread j owns output column j for all 16 rows
    const int j = tid;
    float acc[ROWS];
    #pragma unroll
    for (int r = 0; r < ROWS; r++) acc[r] = 0.f;

    #pragma unroll 4
    for (int k = 0; k < 512; k++) {
        const float wv = W2[(size_t)k * 256 + j];
        #pragma unroll
        for (int r = 0; r < ROWS; r++)
            acc[r] = fmaf(s_t[r * 512 + k], wv, acc[r]);
    }

    // ---- Phase C: gates, liquid update, norm reductions
    const float b2j = b2[j];
    #pragma unroll
    for (int r = 0; r < ROWS; r++) {
        const int rg = row0 + r;
        const float* yrow = g_Y + (size_t)rg * NTOT;
        const float hc = tanhf(acc[r] + b2j);
        const float dp = yrow[512 + j];                  // bias already added
        const float up = yrow[768 + j];
        const float dec = 1.f / (1.f + expf(-dp));
        const float ts  = 0.1f + 9.9f * dec + 1e-6f;
        const float u   = 1.f / (1.f + expf(-up));
        const float hv  = h[(size_t)rg * MEMD + j];
        const float nh  = (1.f - u) * (hv / ts) + u * hc;
        acc[r] = nh;

        float ph = hv * hv, pn = nh * nh;
        #pragma unroll
        for (int o = 16; o; o >>= 1) {
            ph += __shfl_xor_sync(0xffffffffu, ph, o);
            pn += __shfl_xor_sync(0xffffffffu, pn, o);
        }
        if (lane == 0) {
            s_red[r * 8 + w]       = ph;
            s_red[128 + r * 8 + w] = pn;
        }
    }
    __syncthreads();

    if (tid < ROWS) {
        float h2 = 0.f, n2 = 0.f;
        #pragma unroll
        for (int q = 0; q < 8; q++) {
            h2 += s_red[tid * 8 + q];
            n2 += s_red[128 + tid * 8 + q];
        }
        const float hn = fmaxf(sqrtf(h2), 1e-6f);
        const float nn = fmaxf(sqrtf(n2), 1e-12f);
        s_scale[tid] = hn / nn;
    }
    __syncthreads();

    #pragma unroll
    for (int r = 0; r < ROWS; r++)
        out[(size_t)(row0 + r) * MEMD + j] = acc[r] * s_scale[r];
}

// ---------------------------------------------------------------------------
extern "C" void kernel_launch(void* const* d_in, const int* in_sizes, int n_in,
                              void* d_out, int out_size)
{
    (void)in_sizes; (void)n_in; (void)out_size;
    const float* x   = (const float*)d_in[0];
    const float* h   = (const float*)d_in[1];
    const float* W1  = (const float*)d_in[2];
    const float* b1  = (const float*)d_in[3];
    const float* gam = (const float*)d_in[4];
    const float* bet = (const float*)d_in[5];
    const float* W2  = (const float*)d_in[6];
    const float* b2  = (const float*)d_in[7];
    const float* Wd  = (const float*)d_in[8];
    const float* bd  = (const float*)d_in[9];
    const float* Wu  = (const float*)d_in[10];
    const float* bu  = (const float*)d_in[11];
    float* out = (float*)d_out;

    dim3 grid1(NTOT / 128, BATCH / 128);   // 8 x 64
    gemm1_kernel<<<grid1, 256>>>(x, h, W1, Wd, Wu, b1, bd, bu);
    fuse2_kernel<<<BATCH / 16, 256>>>(h, gam, bet, W2, b2, out);
}

// round 6
// speedup vs baseline: 1.8494x; 1.8467x over previous
#include <cuda_runtime.h>
#include <cuda_bf16.h>
#include <math.h>
#include <cstdint>

#define BATCH  8192
#define IN_DIM 4096
#define MEMD   256
#define KDIM   4352
#define NTOT   1024

// gmem scratch
__device__ float        g_Y [(size_t)BATCH * NTOT];
__device__ __nv_bfloat16 g_Ah[(size_t)BATCH * KDIM];
__device__ __nv_bfloat16 g_Al[(size_t)BATCH * KDIM];
__device__ __nv_bfloat16 g_Bh[(size_t)NTOT  * KDIM];
__device__ __nv_bfloat16 g_Bl[(size_t)NTOT  * KDIM];
__device__ float        g_ball[NTOT];

// ------------------------------- helpers ----------------------------------
__device__ __forceinline__ uint32_t smem_u32(const void* p){
    uint32_t a;
    asm("{ .reg .u64 t; cvta.to.shared.u64 t, %1; cvt.u32.u64 %0, t; }" : "=r"(a) : "l"(p));
    return a;
}
__device__ __forceinline__ void splitf(float v, unsigned short& hi, unsigned short& lo){
    __nv_bfloat16 h = __float2bfloat16(v);
    __nv_bfloat16 l = __float2bfloat16(v - __bfloat162float(h));
    hi = __bfloat16_as_ushort(h);
    lo = __bfloat16_as_ushort(l);
}

#define CP_ASYNC16(dst, src) \
    asm volatile("cp.async.cg.shared.global [%0], [%1], 16;" :: "r"(dst), "l"(src))
#define CP_COMMIT() asm volatile("cp.async.commit_group;" ::: "memory")
#define CP_WAIT1()  asm volatile("cp.async.wait_group 1;" ::: "memory")

#define LDSM4(r, addr) \
    asm volatile("ldmatrix.sync.aligned.m8n8.x4.shared.b16 {%0,%1,%2,%3}, [%4];" \
        : "=r"((r)[0]), "=r"((r)[1]), "=r"((r)[2]), "=r"((r)[3]) : "r"(addr))

#define MMA16816(d, a, b0, b1) \
    asm volatile("mma.sync.aligned.m16n8k16.row.col.f32.bf16.bf16.f32 " \
        "{%0,%1,%2,%3}, {%4,%5,%6,%7}, {%8,%9}, {%0,%1,%2,%3};" \
        : "+f"((d)[0]), "+f"((d)[1]), "+f"((d)[2]), "+f"((d)[3]) \
        : "r"((a)[0]), "r"((a)[1]), "r"((a)[2]), "r"((a)[3]), "r"(b0), "r"(b1))

// ---------------------------------------------------------------------------
// Prep A: split [h|x] -> bf16 hi/lo planes, row-major [m][k]
// ---------------------------------------------------------------------------
__global__ __launch_bounds__(256)
void prep_a(const float* __restrict__ x, const float* __restrict__ h)
{
    const int id = blockIdx.x * 256 + threadIdx.x;   // 8192*544 chunks of 8
    const int m  = id / 544;
    const int k  = (id % 544) * 8;
    const float* src = (k < MEMD) ? h + (size_t)m * MEMD + k
                                  : x + (size_t)m * IN_DIM + (k - MEMD);
    float4 v0 = *reinterpret_cast<const float4*>(src);
    float4 v1 = *reinterpret_cast<const float4*>(src + 4);
    float vv[8] = {v0.x, v0.y, v0.z, v0.w, v1.x, v1.y, v1.z, v1.w};
    unsigned short hs[8], ls[8];
    #pragma unroll
    for (int i = 0; i < 8; i++) splitf(vv[i], hs[i], ls[i]);
    uint4 H, L;
    H.x = hs[0] | ((uint32_t)hs[1] << 16);  H.y = hs[2] | ((uint32_t)hs[3] << 16);
    H.z = hs[4] | ((uint32_t)hs[5] << 16);  H.w = hs[6] | ((uint32_t)hs[7] << 16);
    L.x = ls[0] | ((uint32_t)ls[1] << 16);  L.y = ls[2] | ((uint32_t)ls[3] << 16);
    L.z = ls[4] | ((uint32_t)ls[5] << 16);  L.w = ls[6] | ((uint32_t)ls[7] << 16);
    *reinterpret_cast<uint4*>(g_Ah + (size_t)m * KDIM + k) = H;
    *reinterpret_cast<uint4*>(g_Al + (size_t)m * KDIM + k) = L;
}

// ---------------------------------------------------------------------------
// Prep W: transpose+concat [W1|Wd|Wu] (k-major) -> bf16 hi/lo planes [n][k]
// ---------------------------------------------------------------------------
__global__ void prep_w(const float* __restrict__ W1, const float* __restrict__ Wd,
                       const float* __restrict__ Wu,
                       const float* __restrict__ b1, const float* __restrict__ bd,
                       const float* __restrict__ bu)
{
    __shared__ float t[32][33];
    const int k0 = blockIdx.x * 32, n0 = blockIdx.y * 32;
    const int tx = threadIdx.x, ty = threadIdx.y;   // 32 x 8
    const float* Wsrc; int ldw, noff;
    if (n0 < 512)      { Wsrc = W1; ldw = 512; noff = 0; }
    else if (n0 < 768) { Wsrc = Wd; ldw = 256; noff = 512; }
    else               { Wsrc = Wu; ldw = 256; noff = 768; }
    #pragma unroll
    for (int i = 0; i < 4; i++)
        t[ty + 8*i][tx] = Wsrc[(size_t)(k0 + ty + 8*i) * ldw + (n0 - noff) + tx];
    __syncthreads();
    #pragma unroll
    for (int i = 0; i < 4; i++) {
        const int n = n0 + ty + 8*i;
        unsigned short hi, lo;
        splitf(t[tx][ty + 8*i], hi, lo);
        g_Bh[(size_t)n * KDIM + k0 + tx] = __ushort_as_bfloat16(hi);
        g_Bl[(size_t)n * KDIM + k0 + tx] = __ushort_as_bfloat16(lo);
    }
    if (blockIdx.x == 0 && ty == 0) {
        const int n = n0 + tx;
        const float* bsrc = (n < 512) ? b1 : (n < 768 ? bd : bu);
        const int off = (n < 512) ? 0 : (n < 768 ? 512 : 768);
        g_ball[n] = bsrc[n - off];
    }
}

// ---------------------------------------------------------------------------
// GEMM: g_Y = [h|x] @ Wt^T + bias  via HMMA bf16x3 split
// BM=128, BN=128, BK=32; 8 warps (4m x 2n), warp tile 32x64; 3-stage cp.async
// smem plane: 128 rows x 80B (32 bf16 padded) -> LDSM conflict-free
// ---------------------------------------------------------------------------
#define PLANE    10240            // 128*80
#define ST_BYTES 40960            // 4 planes
#define NSTAGE   3
#define SMEM_TOTAL (NSTAGE * ST_BYTES)
#define KSTAGES  (KDIM / 32)      // 136

__global__ __launch_bounds__(256, 1)
void gemm1_mma()
{
    extern __shared__ char smem[];
    const uint32_t sb = smem_u32(smem);
    const int tid  = threadIdx.x;
    const int wid  = tid >> 5;
    const int lane = tid & 31;
    const int bx = blockIdx.x;   // n-tile 0..7
    const int by = blockIdx.y;   // m-tile 0..63

    const __nv_bfloat16* base[4] = {
        g_Ah + (size_t)(by * 128) * KDIM,
        g_Al + (size_t)(by * 128) * KDIM,
        g_Bh + (size_t)(bx * 128) * KDIM,
        g_Bl + (size_t)(bx * 128) * KDIM
    };

    // cp.async mapping: 2048 16B-chunks/stage, 8 per thread, p = i>>1 const
    auto load_stage = [&](int s) {
        const uint32_t st = sb + (uint32_t)(s % NSTAGE) * ST_BYTES;
        const int koff = s * 32;
        #pragma unroll
        for (int i = 0; i < 8; i++) {
            const int p   = i >> 1;
            const int rem = ((i & 1) << 8) | tid;
            const int row = rem >> 2, g = rem & 3;
            const __nv_bfloat16* src = base[p] + (size_t)row * KDIM + koff + g * 8;
            const uint32_t dst = st + p * PLANE + row * 80 + g * 16;
            CP_ASYNC16(dst, src);
        }
        CP_COMMIT();
    };

    const int wm = wid & 3;        // m-warp 0..3
    const int wn = wid >> 2;       // n-warp 0..1
    const int rsel = lane & 15;
    const int bsel = lane >> 4;

    float acc[2][8][4];
    #pragma unroll
    for (int mf = 0; mf < 2; mf++)
        #pragma unroll
        for (int nf = 0; nf < 8; nf++)
            #pragma unroll
            for (int q = 0; q < 4; q++) acc[mf][nf][q] = 0.f;

    load_stage(0);
    load_stage(1);

    #pragma unroll 1
    for (int s = 0; s < KSTAGES; s++) {
        CP_WAIT1();
        __syncthreads();
        if (s + 2 < KSTAGES) load_stage(s + 2);

        const uint32_t st = sb + (uint32_t)(s % NSTAGE) * ST_BYTES;
        #pragma unroll
        for (int kk = 0; kk < 2; kk++) {
            const uint32_t kaddr = (uint32_t)(((kk << 1) + bsel) << 4);
            uint32_t Ah[2][4], Al[2][4], Bh[4][4], Bl[4][4];
            #pragma unroll
            for (int mf = 0; mf < 2; mf++) {
                const uint32_t r = (uint32_t)(wm * 32 + mf * 16 + rsel) * 80;
                LDSM4(Ah[mf], st + 0 * PLANE + r + kaddr);
                LDSM4(Al[mf], st + 1 * PLANE + r + kaddr);
            }
            #pragma unroll
            for (int j = 0; j < 4; j++) {
                const uint32_t r = (uint32_t)(wn * 64 + j * 16 + rsel) * 80;
                LDSM4(Bh[j], st + 2 * PLANE + r + kaddr);
                LDSM4(Bl[j], st + 3 * PLANE + r + kaddr);
            }
            #pragma unroll
            for (int mf = 0; mf < 2; mf++)
                #pragma unroll
                for (int nf = 0; nf < 8; nf++) {
                    const int j = nf >> 1, pp = nf & 1;
                    MMA16816(acc[mf][nf], Ah[mf], Bh[j][pp], Bh[j][2 + pp]);
                    MMA16816(acc[mf][nf], Ah[mf], Bl[j][pp], Bl[j][2 + pp]);
                    MMA16816(acc[mf][nf], Al[mf], Bh[j][pp], Bh[j][2 + pp]);
                }
        }
    }

    // epilogue: add bias, store fp32
    const int g  = lane >> 2;
    const int t2 = (lane & 3) * 2;
    const int ncol0 = bx * 128 + wn * 64;
    #pragma unroll
    for (int mf = 0; mf < 2; mf++) {
        const int m = by * 128 + wm * 32 + mf * 16 + g;
        float* y0 = g_Y + (size_t)m * NTOT + ncol0;
        float* y1 = y0 + (size_t)8 * NTOT;
        #pragma unroll
        for (int nf = 0; nf < 8; nf++) {
            const int nn = nf * 8 + t2;
            const float bz0 = g_ball[ncol0 + nn];
            const float bz1 = g_ball[ncol0 + nn + 1];
            float2 u0 = make_float2(acc[mf][nf][0] + bz0, acc[mf][nf][1] + bz1);
            float2 u1 = make_float2(acc[mf][nf][2] + bz0, acc[mf][nf][3] + bz1);
            *reinterpret_cast<float2*>(y0 + nn) = u0;
            *reinterpret_cast<float2*>(y1 + nn) = u1;
        }
    }
}

// ---------------------------------------------------------------------------
// Kernel 2: LN + exact GELU + GEMM2 + gates + L2 renorm (unchanged)
// ---------------------------------------------------------------------------
__global__ __launch_bounds__(256)
void fuse2_kernel(const float* __restrict__ h,
                  const float* __restrict__ gam, const float* __restrict__ bet,
                  const float* __restrict__ W2, const float* __restrict__ b2,
                  float* __restrict__ out)
{
    constexpr int ROWS = 16;
    __shared__ float s_t[ROWS * 512];
    __shared__ float s_red[2 * ROWS * 8];
    __shared__ float s_scale[ROWS];

    const int tid  = threadIdx.x;
    const int w    = tid >> 5;
    const int lane = tid & 31;
    const int row0 = blockIdx.x * ROWS;

    #pragma unroll
    for (int rr = 0; rr < 2; ++rr) {
        const int r = w + rr * 8;
        const float* yrow = g_Y + (size_t)(row0 + r) * NTOT;
        float vals[16];
        float s = 0.f, s2 = 0.f;
        #pragma unroll
        for (int q = 0; q < 4; q++) {
            float4 v = *reinterpret_cast<const float4*>(yrow + (lane + q * 32) * 4);
            vals[q*4+0] = v.x; vals[q*4+1] = v.y; vals[q*4+2] = v.z; vals[q*4+3] = v.w;
            s  += v.x + v.y + v.z + v.w;
            s2 += v.x*v.x + v.y*v.y + v.z*v.z + v.w*v.w;
        }
        #pragma unroll
        for (int o = 16; o; o >>= 1) {
            s  += __shfl_xor_sync(0xffffffffu, s,  o);
            s2 += __shfl_xor_sync(0xffffffffu, s2, o);
        }
        const float mu   = s * (1.f / 512.f);
        const float var  = s2 * (1.f / 512.f) - mu * mu;
        const float rstd = rsqrtf(var + 1e-5f);
        #pragma unroll
        for (int q = 0; q < 4; q++) {
            const int c = (lane + q * 32) * 4;
            float4 gv = *reinterpret_cast<const float4*>(gam + c);
            float4 bv = *reinterpret_cast<const float4*>(bet + c);
            float g4[4]  = {gv.x, gv.y, gv.z, gv.w};
            float be4[4] = {bv.x, bv.y, bv.z, bv.w};
            #pragma unroll
            for (int e = 0; e < 4; e++) {
                float t = (vals[q*4+e] - mu) * rstd * g4[e] + be4[e];
                s_t[r * 512 + c + e] = 0.5f * t * (1.f + erff(t * 0.7071067811865475f));
            }
        }
    }
    __syncthreads();

    const int j = tid;
    float acc[ROWS];
    #pragma unroll
    for (int r = 0; r < ROWS; r++) acc[r] = 0.f;
    #pragma unroll 4
    for (int k = 0; k < 512; k++) {
        const float wv = W2[(size_t)k * 256 + j];
        #pragma unroll
        for (int r = 0; r < ROWS; r++)
            acc[r] = fmaf(s_t[r * 512 + k], wv, acc[r]);
    }

    const float b2j = b2[j];
    #pragma unroll
    for (int r = 0; r < ROWS; r++) {
        const int rg = row0 + r;
        const float* yrow = g_Y + (size_t)rg * NTOT;
        const float hc  = tanhf(acc[r] + b2j);
        const float dec = 1.f / (1.f + expf(-yrow[512 + j]));
        const float ts  = 0.1f + 9.9f * dec + 1e-6f;
        const float u   = 1.f / (1.f + expf(-yrow[768 + j]));
        const float hv  = h[(size_t)rg * MEMD + j];
        const float nh  = (1.f - u) * (hv / ts) + u * hc;
        acc[r] = nh;
        float ph = hv * hv, pn = nh * nh;
        #pragma unroll
        for (int o = 16; o; o >>= 1) {
            ph += __shfl_xor_sync(0xffffffffu, ph, o);
            pn += __shfl_xor_sync(0xffffffffu, pn, o);
        }
        if (lane == 0) { s_red[r*8 + w] = ph; s_red[128 + r*8 + w] = pn; }
    }
    __syncthreads();

    if (tid < ROWS) {
        float h2 = 0.f, n2 = 0.f;
        #pragma unroll
        for (int q = 0; q < 8; q++) { h2 += s_red[tid*8+q]; n2 += s_red[128 + tid*8+q]; }
        s_scale[tid] = fmaxf(sqrtf(h2), 1e-6f) / fmaxf(sqrtf(n2), 1e-12f);
    }
    __syncthreads();

    #pragma unroll
    for (int r = 0; r < ROWS; r++)
        out[(size_t)(row0 + r) * MEMD + j] = acc[r] * s_scale[r];
}

// ---------------------------------------------------------------------------
extern "C" void kernel_launch(void* const* d_in, const int* in_sizes, int n_in,
                              void* d_out, int out_size)
{
    (void)in_sizes; (void)n_in; (void)out_size;
    const float* x   = (const float*)d_in[0];
    const float* h   = (const float*)d_in[1];
    const float* W1  = (const float*)d_in[2];
    const float* b1  = (const float*)d_in[3];
    const float* gam = (const float*)d_in[4];
    const float* bet = (const float*)d_in[5];
    const float* W2  = (const float*)d_in[6];
    const float* b2  = (const float*)d_in[7];
    const float* Wd  = (const float*)d_in[8];
    const float* bd  = (const float*)d_in[9];
    const float* Wu  = (const float*)d_in[10];
    const float* bu  = (const float*)d_in[11];
    float* out = (float*)d_out;

    cudaFuncSetAttribute(gemm1_mma, cudaFuncAttributeMaxDynamicSharedMemorySize, SMEM_TOTAL);

    prep_a<<<(BATCH * (KDIM / 8)) / 256, 256>>>(x, h);
    prep_w<<<dim3(KDIM / 32, NTOT / 32), dim3(32, 8)>>>(W1, Wd, Wu, b1, bd, bu);

    dim3 ggrid(NTOT / 128, BATCH / 128);   // 8 x 64
    gemm1_mma<<<ggrid, 256, SMEM_TOTAL>>>();

    fuse2_kernel<<<BATCH / 16, 256>>>(h, gam, bet, W2, b2, out);
}

// round 7
// speedup vs baseline: 2.1804x; 1.1790x over previous
#include <cuda_runtime.h>
#include <cuda_bf16.h>
#include <math.h>
#include <cstdint>

#define BATCH  8192
#define IN_DIM 4096
#define MEMD   256
#define KDIM   4352
#define NTOT   1024

// gmem scratch
__device__ float         g_Y [(size_t)BATCH * NTOT];
__device__ __nv_bfloat16 g_Ah[(size_t)BATCH * KDIM];
__device__ __nv_bfloat16 g_Al[(size_t)BATCH * KDIM];
__device__ __nv_bfloat16 g_Bh[(size_t)NTOT  * KDIM];
__device__ __nv_bfloat16 g_Bl[(size_t)NTOT  * KDIM];
__device__ float         g_ball[NTOT];

// ------------------------------- helpers ----------------------------------
__device__ __forceinline__ uint32_t smem_u32(const void* p){
    uint32_t a;
    asm("{ .reg .u64 t; cvta.to.shared.u64 t, %1; cvt.u32.u64 %0, t; }" : "=r"(a) : "l"(p));
    return a;
}
__device__ __forceinline__ void splitf(float v, unsigned short& hi, unsigned short& lo){
    __nv_bfloat16 h = __float2bfloat16(v);
    __nv_bfloat16 l = __float2bfloat16(v - __bfloat162float(h));
    hi = __bfloat16_as_ushort(h);
    lo = __bfloat16_as_ushort(l);
}

#define CP_ASYNC16(dst, src) \
    asm volatile("cp.async.cg.shared.global [%0], [%1], 16;" :: "r"(dst), "l"(src))
#define CP_COMMIT() asm volatile("cp.async.commit_group;" ::: "memory")
#define CP_WAIT1()  asm volatile("cp.async.wait_group 1;" ::: "memory")
#define CP_WAIT0()  asm volatile("cp.async.wait_group 0;" ::: "memory")

#define LDSM4(r, addr) \
    asm volatile("ldmatrix.sync.aligned.m8n8.x4.shared.b16 {%0,%1,%2,%3}, [%4];" \
        : "=r"((r)[0]), "=r"((r)[1]), "=r"((r)[2]), "=r"((r)[3]) : "r"(addr))

#define MMA16816(d, a, b0, b1) \
    asm volatile("mma.sync.aligned.m16n8k16.row.col.f32.bf16.bf16.f32 " \
        "{%0,%1,%2,%3}, {%4,%5,%6,%7}, {%8,%9}, {%0,%1,%2,%3};" \
        : "+f"((d)[0]), "+f"((d)[1]), "+f"((d)[2]), "+f"((d)[3]) \
        : "r"((a)[0]), "r"((a)[1]), "r"((a)[2]), "r"((a)[3]), "r"(b0), "r"(b1))

// ---------------------------------------------------------------------------
// Prep A: split [h|x] -> bf16 hi/lo planes, row-major [m][k]
// ---------------------------------------------------------------------------
__global__ __launch_bounds__(256)
void prep_a(const float* __restrict__ x, const float* __restrict__ h)
{
    const int id = blockIdx.x * 256 + threadIdx.x;
    const int m  = id / 544;
    const int k  = (id % 544) * 8;
    const float* src = (k < MEMD) ? h + (size_t)m * MEMD + k
                                  : x + (size_t)m * IN_DIM + (k - MEMD);
    float4 v0 = *reinterpret_cast<const float4*>(src);
    float4 v1 = *reinterpret_cast<const float4*>(src + 4);
    float vv[8] = {v0.x, v0.y, v0.z, v0.w, v1.x, v1.y, v1.z, v1.w};
    unsigned short hs[8], ls[8];
    #pragma unroll
    for (int i = 0; i < 8; i++) splitf(vv[i], hs[i], ls[i]);
    uint4 H, L;
    H.x = hs[0] | ((uint32_t)hs[1] << 16);  H.y = hs[2] | ((uint32_t)hs[3] << 16);
    H.z = hs[4] | ((uint32_t)hs[5] << 16);  H.w = hs[6] | ((uint32_t)hs[7] << 16);
    L.x = ls[0] | ((uint32_t)ls[1] << 16);  L.y = ls[2] | ((uint32_t)ls[3] << 16);
    L.z = ls[4] | ((uint32_t)ls[5] << 16);  L.w = ls[6] | ((uint32_t)ls[7] << 16);
    *reinterpret_cast<uint4*>(g_Ah + (size_t)m * KDIM + k) = H;
    *reinterpret_cast<uint4*>(g_Al + (size_t)m * KDIM + k) = L;
}

// ---------------------------------------------------------------------------
// Prep W: transpose+concat [W1|Wd|Wu] -> bf16 hi/lo planes [n][k]
// ---------------------------------------------------------------------------
__global__ void prep_w(const float* __restrict__ W1, const float* __restrict__ Wd,
                       const float* __restrict__ Wu,
                       const float* __restrict__ b1, const float* __restrict__ bd,
                       const float* __restrict__ bu)
{
    __shared__ float t[32][33];
    const int k0 = blockIdx.x * 32, n0 = blockIdx.y * 32;
    const int tx = threadIdx.x, ty = threadIdx.y;
    const float* Wsrc; int ldw, noff;
    if (n0 < 512)      { Wsrc = W1; ldw = 512; noff = 0; }
    else if (n0 < 768) { Wsrc = Wd; ldw = 256; noff = 512; }
    else               { Wsrc = Wu; ldw = 256; noff = 768; }
    #pragma unroll
    for (int i = 0; i < 4; i++)
        t[ty + 8*i][tx] = Wsrc[(size_t)(k0 + ty + 8*i) * ldw + (n0 - noff) + tx];
    __syncthreads();
    #pragma unroll
    for (int i = 0; i < 4; i++) {
        const int n = n0 + ty + 8*i;
        unsigned short hi, lo;
        splitf(t[tx][ty + 8*i], hi, lo);
        g_Bh[(size_t)n * KDIM + k0 + tx] = __ushort_as_bfloat16(hi);
        g_Bl[(size_t)n * KDIM + k0 + tx] = __ushort_as_bfloat16(lo);
    }
    if (blockIdx.x == 0 && ty == 0) {
        const int n = n0 + tx;
        const float* bsrc = (n < 512) ? b1 : (n < 768 ? bd : bu);
        const int off = (n < 512) ? 0 : (n < 768 ? 512 : 768);
        g_ball[n] = bsrc[n - off];
    }
}

// ---------------------------------------------------------------------------
// GEMM: BM=128, BN=256, BK=64; 512 thr (warp grid 4m x 4n, warp tile 32x64);
// 2-stage cp.async; smem rows padded to 144B (conflict-free LDSM).
// ---------------------------------------------------------------------------
#define ROWB     144
#define OFF_AH   0
#define OFF_AL   18432            // 128*144
#define OFF_BH   36864
#define OFF_BL   73728            // + 256*144
#define ST_BYTES 110592           // 108KB per stage
#define SMEM_TOTAL (2 * ST_BYTES) // 216KB
#define KSTAGES  (KDIM / 64)      // 68

__global__ __launch_bounds__(512, 1)
void gemm1_mma()
{
    extern __shared__ char smem[];
    const uint32_t sb = smem_u32(smem);
    const int tid  = threadIdx.x;
    const int wid  = tid >> 5;
    const int lane = tid & 31;
    const int bx = blockIdx.x;   // n-tile 0..3
    const int by = blockIdx.y;   // m-tile 0..63

    const __nv_bfloat16* baseA[2] = {
        g_Ah + (size_t)(by * 128) * KDIM,
        g_Al + (size_t)(by * 128) * KDIM
    };
    const __nv_bfloat16* baseB[2] = {
        g_Bh + (size_t)(bx * 256) * KDIM,
        g_Bl + (size_t)(bx * 256) * KDIM
    };

    // 6144 16B-chunks per stage, 12 per thread
    auto load_stage = [&](int s) {
        const uint32_t st = sb + (uint32_t)(s & 1) * ST_BYTES;
        const int koff = s * 64;
        #pragma unroll
        for (int t = 0; t < 12; t++) {
            const int c = t * 512 + tid;
            const __nv_bfloat16* src;
            uint32_t dst;
            if (c < 2048) {                   // A planes
                const int p = c >> 10, idx = c & 1023;
                const int row = idx >> 3, g = idx & 7;
                src = baseA[p] + (size_t)row * KDIM + koff + g * 8;
                dst = st + (p ? OFF_AL : OFF_AH) + row * ROWB + g * 16;
            } else {                          // B planes
                const int c2 = c - 2048;
                const int p = c2 >> 11, idx = c2 & 2047;
                const int row = idx >> 3, g = idx & 7;
                src = baseB[p] + (size_t)row * KDIM + koff + g * 8;
                dst = st + (p ? OFF_BL : OFF_BH) + row * ROWB + g * 16;
            }
            CP_ASYNC16(dst, src);
        }
        CP_COMMIT();
    };

    const int wm = wid & 3;        // m-warp 0..3
    const int wn = wid >> 2;       // n-warp 0..3
    const int rsel = lane & 15;
    const int bsel = lane >> 4;

    float acc[2][8][4];
    #pragma unroll
    for (int mf = 0; mf < 2; mf++)
        #pragma unroll
        for (int nf = 0; nf < 8; nf++)
            #pragma unroll
            for (int q = 0; q < 4; q++) acc[mf][nf][q] = 0.f;

    load_stage(0);
    load_stage(1);

    #pragma unroll 1
    for (int s = 0; s < KSTAGES; s++) {
        if (s + 1 < KSTAGES) { CP_WAIT1(); } else { CP_WAIT0(); }
        __syncthreads();

        const uint32_t st = sb + (uint32_t)(s & 1) * ST_BYTES;
        const uint32_t ra = (uint32_t)(wm * 32 + rsel) * ROWB;
        const uint32_t rb = (uint32_t)(wn * 64 + rsel) * ROWB;

        #pragma unroll
        for (int kk = 0; kk < 4; kk++) {
            const uint32_t kaddr = (uint32_t)(((kk << 1) + bsel) << 4);
            uint32_t Ah[2][4], Al[2][4];
            #pragma unroll
            for (int mf = 0; mf < 2; mf++) {
                const uint32_t r = ra + (uint32_t)(mf * 16) * ROWB + kaddr;
                LDSM4(Ah[mf], st + OFF_AH + r);
                LDSM4(Al[mf], st + OFF_AL + r);
            }
            #pragma unroll
            for (int j = 0; j < 4; j++) {
                uint32_t Bh[4], Bl[4];
                const uint32_t r = rb + (uint32_t)(j * 16) * ROWB + kaddr;
                LDSM4(Bh, st + OFF_BH + r);
                LDSM4(Bl, st + OFF_BL + r);
                #pragma unroll
                for (int mf = 0; mf < 2; mf++)
                    #pragma unroll
                    for (int pp = 0; pp < 2; pp++) {
                        const int nf = j * 2 + pp;
                        MMA16816(acc[mf][nf], Ah[mf], Bh[pp], Bh[2 + pp]);
                        MMA16816(acc[mf][nf], Ah[mf], Bl[pp], Bl[2 + pp]);
                        MMA16816(acc[mf][nf], Al[mf], Bh[pp], Bh[2 + pp]);
                    }
            }
        }

        if (s + 2 < KSTAGES) {
            __syncthreads();
            load_stage(s + 2);
        }
    }

    // epilogue: add bias, store fp32
    const int g  = lane >> 2;
    const int t2 = (lane & 3) * 2;
    const int ncol0 = bx * 256 + wn * 64;
    #pragma unroll
    for (int mf = 0; mf < 2; mf++) {
        const int m = by * 128 + wm * 32 + mf * 16 + g;
        float* y0 = g_Y + (size_t)m * NTOT + ncol0;
        float* y1 = y0 + (size_t)8 * NTOT;
        #pragma unroll
        for (int nf = 0; nf < 8; nf++) {
            const int nn = nf * 8 + t2;
            const float bz0 = g_ball[ncol0 + nn];
            const float bz1 = g_ball[ncol0 + nn + 1];
            *reinterpret_cast<float2*>(y0 + nn) =
                make_float2(acc[mf][nf][0] + bz0, acc[mf][nf][1] + bz1);
            *reinterpret_cast<float2*>(y1 + nn) =
                make_float2(acc[mf][nf][2] + bz0, acc[mf][nf][3] + bz1);
        }
    }
}

// ---------------------------------------------------------------------------
// Kernel 2: LN + exact GELU + GEMM2 + gates + L2 renorm
// ---------------------------------------------------------------------------
__global__ __launch_bounds__(256)
void fuse2_kernel(const float* __restrict__ h,
                  const float* __restrict__ gam, const float* __restrict__ bet,
                  const float* __restrict__ W2, const float* __restrict__ b2,
                  float* __restrict__ out)
{
    constexpr int ROWS = 16;
    __shared__ float s_t[ROWS * 512];
    __shared__ float s_red[2 * ROWS * 8];
    __shared__ float s_scale[ROWS];

    const int tid  = threadIdx.x;
    const int w    = tid >> 5;
    const int lane = tid & 31;
    const int row0 = blockIdx.x * ROWS;

    #pragma unroll
    for (int rr = 0; rr < 2; ++rr) {
        const int r = w + rr * 8;
        const float* yrow = g_Y + (size_t)(row0 + r) * NTOT;
        float vals[16];
        float s = 0.f, s2 = 0.f;
        #pragma unroll
        for (int q = 0; q < 4; q++) {
            float4 v = *reinterpret_cast<const float4*>(yrow + (lane + q * 32) * 4);
            vals[q*4+0] = v.x; vals[q*4+1] = v.y; vals[q*4+2] = v.z; vals[q*4+3] = v.w;
            s  += v.x + v.y + v.z + v.w;
            s2 += v.x*v.x + v.y*v.y + v.z*v.z + v.w*v.w;
        }
        #pragma unroll
        for (int o = 16; o; o >>= 1) {
            s  += __shfl_xor_sync(0xffffffffu, s,  o);
            s2 += __shfl_xor_sync(0xffffffffu, s2, o);
        }
        const float mu   = s * (1.f / 512.f);
        const float var  = s2 * (1.f / 512.f) - mu * mu;
        const float rstd = rsqrtf(var + 1e-5f);
        #pragma unroll
        for (int q = 0; q < 4; q++) {
            const int c = (lane + q * 32) * 4;
            float4 gv = *reinterpret_cast<const float4*>(gam + c);
            float4 bv = *reinterpret_cast<const float4*>(bet + c);
            float g4[4]  = {gv.x, gv.y, gv.z, gv.w};
            float be4[4] = {bv.x, bv.y, bv.z, bv.w};
            #pragma unroll
            for (int e = 0; e < 4; e++) {
                float t = (vals[q*4+e] - mu) * rstd * g4[e] + be4[e];
                s_t[r * 512 + c + e] = 0.5f * t * (1.f + erff(t * 0.7071067811865475f));
            }
        }
    }
    __syncthreads();

    // GEMM2: thread j owns column j; k stepped by 4 with float4 LDS broadcasts
    const int j = tid;
    float acc[ROWS];
    #pragma unroll
    for (int r = 0; r < ROWS; r++) acc[r] = 0.f;

    #pragma unroll 2
    for (int k0 = 0; k0 < 512; k0 += 4) {
        float w0 = W2[(size_t)(k0 + 0) * 256 + j];
        float w1 = W2[(size_t)(k0 + 1) * 256 + j];
        float w2 = W2[(size_t)(k0 + 2) * 256 + j];
        float w3 = W2[(size_t)(k0 + 3) * 256 + j];
        #pragma unroll
        for (int r = 0; r < ROWS; r++) {
            float4 tv = *reinterpret_cast<const float4*>(&s_t[r * 512 + k0]);
            acc[r] = fmaf(tv.x, w0, acc[r]);
            acc[r] = fmaf(tv.y, w1, acc[r]);
            acc[r] = fmaf(tv.z, w2, acc[r]);
            acc[r] = fmaf(tv.w, w3, acc[r]);
        }
    }

    const float b2j = b2[j];
    #pragma unroll
    for (int r = 0; r < ROWS; r++) {
        const int rg = row0 + r;
        const float* yrow = g_Y + (size_t)rg * NTOT;
        const float hc  = tanhf(acc[r] + b2j);
        const float dec = 1.f / (1.f + __expf(-yrow[512 + j]));
        const float ts  = 0.1f + 9.9f * dec + 1e-6f;
        const float u   = 1.f / (1.f + __expf(-yrow[768 + j]));
        const float hv  = h[(size_t)rg * MEMD + j];
        const float nh  = (1.f - u) * (hv / ts) + u * hc;
        acc[r] = nh;
        float ph = hv * hv, pn = nh * nh;
        #pragma unroll
        for (int o = 16; o; o >>= 1) {
            ph += __shfl_xor_sync(0xffffffffu, ph, o);
            pn += __shfl_xor_sync(0xffffffffu, pn, o);
        }
        if (lane == 0) { s_red[r*8 + w] = ph; s_red[128 + r*8 + w] = pn; }
    }
    __syncthreads();

    if (tid < ROWS) {
        float h2 = 0.f, n2 = 0.f;
        #pragma unroll
        for (int q = 0; q < 8; q++) { h2 += s_red[tid*8+q]; n2 += s_red[128 + tid*8+q]; }
        s_scale[tid] = fmaxf(sqrtf(h2), 1e-6f) / fmaxf(sqrtf(n2), 1e-12f);
    }
    __syncthreads();

    #pragma unroll
    for (int r = 0; r < ROWS; r++)
        out[(size_t)(row0 + r) * MEMD + j] = acc[r] * s_scale[r];
}

// ---------------------------------------------------------------------------
extern "C" void kernel_launch(void* const* d_in, const int* in_sizes, int n_in,
                              void* d_out, int out_size)
{
    (void)in_sizes; (void)n_in; (void)out_size;
    const float* x   = (const float*)d_in[0];
    const float* h   = (const float*)d_in[1];
    const float* W1  = (const float*)d_in[2];
    const float* b1  = (const float*)d_in[3];
    const float* gam = (const float*)d_in[4];
    const float* bet = (const float*)d_in[5];
    const float* W2  = (const float*)d_in[6];
    const float* b2  = (const float*)d_in[7];
    const float* Wd  = (const float*)d_in[8];
    const float* bd  = (const float*)d_in[9];
    const float* Wu  = (const float*)d_in[10];
    const float* bu  = (const float*)d_in[11];
    float* out = (float*)d_out;

    cudaFuncSetAttribute(gemm1_mma, cudaFuncAttributeMaxDynamicSharedMemorySize, SMEM_TOTAL);

    prep_a<<<(BATCH * (KDIM / 8)) / 256, 256>>>(x, h);
    prep_w<<<dim3(KDIM / 32, NTOT / 32), dim3(32, 8)>>>(W1, Wd, Wu, b1, bd, bu);

    dim3 ggrid(NTOT / 256, BATCH / 128);   // 4 x 64
    gemm1_mma<<<ggrid, 512, SMEM_TOTAL>>>();

    fuse2_kernel<<<BATCH / 16, 256>>>(h, gam, bet, W2, b2, out);
}